// round 5
// baseline (speedup 1.0000x reference)
#include <cuda_runtime.h>
#include <cuda_bf16.h>
#include <cstdint>

#define N_NODES   50000
#define N_EDGES   800000
#define N_FEAT    128
#define HIDDEN    64
#define N_GRAPHS  256
#define NB_SCAN   196               // 196*256 = 50176 >= N_NODES
#define NB_GEMM   782               // ceil(50000/64)
#define NB_FILL   782               // ceil(800000/4/256)

// ---------------- scratch ----------------------------------------------------
__device__ __align__(16) int    d_src[N_EDGES];
__device__ __align__(16) int    d_dst[N_EDGES];
__device__ __align__(16) int2   d_csr[N_EDGES];    // {src, bits(dis[src])}
__device__ int    d_batch[N_NODES];
__device__ int    d_flag;
__device__ int    d_ecnt[N_NODES];
__device__ int    d_ptr[N_NODES];
__device__ int    d_cur[N_NODES];
__device__ int    d_bagg[NB_SCAN];
__device__ int    d_binc[NB_SCAN];
__device__ int    d_bflag[NB_SCAN];
__device__ float  d_dis[N_NODES + 1];              // +1: zero-row entry
__device__ __align__(16) float2 d_ga[(N_NODES + 1) * 32];  // X@W1 (unscaled) + zero row
__device__ __align__(16) float2 d_gb[(N_NODES + 1) * 32];  // h@W2 (unscaled) + zero row
__device__ float  d_pool[N_GRAPHS * HIDDEN];
__device__ float  d_cnt[N_GRAPHS];

// ---------------- prep: zero scratch + dtype flag ------------------------------
__global__ void k_prep(const int* __restrict__ ebuf) {
    int i = blockIdx.x * blockDim.x + threadIdx.x;
    if (i < N_NODES) d_ecnt[i] = 0;
    if (i < N_GRAPHS * HIDDEN) d_pool[i] = 0.f;
    if (i < N_GRAPHS) d_cnt[i] = 0.f;
    if (i < NB_SCAN) d_bflag[i] = 0;
    if (i < 32) {
        d_ga[N_NODES * 32 + i] = make_float2(0.f, 0.f);
        d_gb[N_NODES * 32 + i] = make_float2(0.f, 0.f);
        if (i == 0) d_dis[N_NODES] = 0.f;
    }
    if (blockIdx.x == 0) {
        __shared__ int ok;
        if (threadIdx.x == 0) ok = 1;
        __syncthreads();
        int bad = 0;
        for (int t = threadIdx.x; t < 1024; t += blockDim.x)
            if (ebuf[2 * t + 1] != 0) bad = 1;
        if (bad) ok = 0;
        __syncthreads();
        if (threadIdx.x == 0) d_flag = ok;
    }
}

// ---------------- convert (4 edges/thread) + histogram + batch -----------------
__global__ void k_convert(const void* __restrict__ e, const void* __restrict__ b) {
    int t = blockIdx.x * blockDim.x + threadIdx.x;
    int f = d_flag;
    int e0 = t * 4;
    if (e0 < N_EDGES) {
        int s[4], dd[4];
        if (f) {
            const long long* p = (const long long*)e;
#pragma unroll
            for (int k = 0; k < 4; k++) { s[k] = (int)p[e0 + k]; dd[k] = (int)p[e0 + k + N_EDGES]; }
        } else {
            const int* p = (const int*)e;
#pragma unroll
            for (int k = 0; k < 4; k++) { s[k] = p[e0 + k]; dd[k] = p[e0 + k + N_EDGES]; }
        }
        ((int4*)d_src)[t] = make_int4(s[0], s[1], s[2], s[3]);
        ((int4*)d_dst)[t] = make_int4(dd[0], dd[1], dd[2], dd[3]);
#pragma unroll
        for (int k = 0; k < 4; k++) atomicAdd(&d_ecnt[dd[k]], 1);
    }
    if (t < N_NODES) {
        int bb = f ? (int)((const long long*)b)[t] : ((const int*)b)[t];
        d_batch[t] = bb;
        atomicAdd(&d_cnt[bb], 1.0f);
    }
}

// ---------------- single-pass scan (decoupled lookback) ------------------------
__global__ void __launch_bounds__(256) k_scan() {
    __shared__ int sm[256];
    __shared__ int s_exc;
    int t = threadIdx.x, bid = blockIdx.x;
    int i = bid * 256 + t;
    int v = (i < N_NODES) ? d_ecnt[i] : 0;
    sm[t] = v;
    __syncthreads();
    for (int off = 1; off < 256; off <<= 1) {
        int u = (t >= off) ? sm[t - off] : 0;
        __syncthreads();
        sm[t] += u;
        __syncthreads();
    }
    int incl = sm[t];
    int total = sm[255];
    if (t == 0) {
        d_bagg[bid] = total;
        __threadfence();
        d_bflag[bid] = 1;
    }
    if (t < 32) {
        int sum = 0;
        int pos = bid - 1;
        while (pos >= 0) {
            int p = pos - t;
            int fl = 0, val = 0;
            if (p >= 0) {
                do { fl = ((volatile int*)d_bflag)[p]; } while (fl == 0);
                val = (fl == 2) ? ((volatile int*)d_binc)[p]
                                : ((volatile int*)d_bagg)[p];
            }
            unsigned ball = __ballot_sync(0xffffffffu, fl == 2 && p >= 0);
            if (ball) {
                int lead = __ffs(ball) - 1;
                sum += (t <= lead) ? val : 0;
                pos = -1;
            } else {
                sum += (p >= 0) ? val : 0;
                pos -= 32;
            }
        }
        for (int o = 16; o; o >>= 1) sum += __shfl_down_sync(0xffffffffu, sum, o);
        if (t == 0) {
            s_exc = sum;
            d_binc[bid] = sum + total;
            __threadfence();
            d_bflag[bid] = 2;
        }
    }
    __syncthreads();
    if (i < N_NODES) {
        int p = s_exc + incl - v;
        d_ptr[i] = p;
        d_cur[i] = p;
        d_dis[i] = rsqrtf((float)(v + 1));
    }
}

// ---------------- fat kernel: gemm1 blocks + fill blocks -----------------------
// gemm: Ga = X @ W1 (UNSCALED).  fill: csr[pos] = {src, dis[src]}
__global__ void __launch_bounds__(256) k_fill_gemm(const float* __restrict__ X,
                                                   const float* __restrict__ W) {
    __shared__ float4 sw[N_FEAT * 16];       // 32 KB (gemm blocks only)
    __shared__ float  sx[64][N_FEAT];        // 32 KB
    int tid = threadIdx.x;
    if (blockIdx.x >= NB_GEMM) {
        // ----- fill part -----
        int t = (blockIdx.x - NB_GEMM) * 256 + tid;
        int e0 = t * 4;
        if (e0 >= N_EDGES) return;
        int4 s4 = ((const int4*)d_src)[t];
        int4 d4 = ((const int4*)d_dst)[t];
        float f0 = d_dis[s4.x], f1 = d_dis[s4.y], f2 = d_dis[s4.z], f3 = d_dis[s4.w];
        int p0 = atomicAdd(&d_cur[d4.x], 1);
        int p1 = atomicAdd(&d_cur[d4.y], 1);
        int p2 = atomicAdd(&d_cur[d4.z], 1);
        int p3 = atomicAdd(&d_cur[d4.w], 1);
        d_csr[p0] = make_int2(s4.x, __float_as_int(f0));
        d_csr[p1] = make_int2(s4.y, __float_as_int(f1));
        d_csr[p2] = make_int2(s4.z, __float_as_int(f2));
        d_csr[p3] = make_int2(s4.w, __float_as_int(f3));
        return;
    }
    // ----- gemm part -----
    int w = tid >> 5, lane = tid & 31, h = lane >> 4, l16 = lane & 15;
    for (int i = tid; i < N_FEAT * 16; i += 256) sw[i] = ((const float4*)W)[i];
    int row0 = blockIdx.x * 64;
    const float4* X4 = (const float4*)X;
    for (int i = tid; i < 64 * 32; i += 256) {
        int r = i >> 5, c = i & 31;
        int row = row0 + r;
        float4 v = (row < N_NODES) ? X4[row * 32 + c] : make_float4(0.f, 0.f, 0.f, 0.f);
        ((float4*)&sx[r][0])[c] = v;
    }
    __syncthreads();
    int rbase = w * 8 + h * 4;
    float4 a0 = {0,0,0,0}, a1 = {0,0,0,0}, a2 = {0,0,0,0}, a3 = {0,0,0,0};
#pragma unroll 8
    for (int k = 0; k < N_FEAT; k++) {
        float4 wv = sw[k * 16 + l16];
        float x0 = sx[rbase + 0][k];
        float x1 = sx[rbase + 1][k];
        float x2 = sx[rbase + 2][k];
        float x3 = sx[rbase + 3][k];
        a0.x += x0*wv.x; a0.y += x0*wv.y; a0.z += x0*wv.z; a0.w += x0*wv.w;
        a1.x += x1*wv.x; a1.y += x1*wv.y; a1.z += x1*wv.z; a1.w += x1*wv.w;
        a2.x += x2*wv.x; a2.y += x2*wv.y; a2.z += x2*wv.z; a2.w += x2*wv.w;
        a3.x += x3*wv.x; a3.y += x3*wv.y; a3.z += x3*wv.z; a3.w += x3*wv.w;
    }
    float4 acc[4] = {a0, a1, a2, a3};
#pragma unroll
    for (int i = 0; i < 4; i++) {
        int row = row0 + rbase + i;
        if (row < N_NODES)
            ((float4*)d_ga)[row * 16 + l16] = acc[i];
    }
}

// ---------------- CSR gather (full warp float2, 16 loads in flight) ------------
__device__ __forceinline__ float2 agg_node(const float2* __restrict__ g2,
                                           int node, int lane) {
    int start = d_ptr[node];
    int n = d_ecnt[node];
    float sl = d_dis[node];
    float2 self = g2[node * 32 + lane];
    float2 aA = make_float2(sl * self.x, sl * self.y);   // self-loop: dis[n]*g[n]
    float2 aB = make_float2(0.f, 0.f);
    float2 aC = make_float2(0.f, 0.f);
    float2 aD = make_float2(0.f, 0.f);
    for (int base = 0; base < n; base += 32) {
        int rem = n - base;
        int2 ev = (lane < rem) ? d_csr[start + base + lane] : make_int2(N_NODES, 0);
        int mm = rem < 32 ? rem : 32;
#pragma unroll 1
        for (int jj = 0; jj < mm; jj += 16) {
#pragma unroll
            for (int j = 0; j < 16; j++) {
                int   s  = __shfl_sync(0xffffffffu, ev.x, jj + j);
                float ds = __int_as_float(__shfl_sync(0xffffffffu, ev.y, jj + j));
                float2 a = g2[s * 32 + lane];
                switch (j & 3) {
                    case 0: aA.x += ds * a.x; aA.y += ds * a.y; break;
                    case 1: aB.x += ds * a.x; aB.y += ds * a.y; break;
                    case 2: aC.x += ds * a.x; aC.y += ds * a.y; break;
                    default: aD.x += ds * a.x; aD.y += ds * a.y; break;
                }
            }
        }
    }
    return make_float2((aA.x + aB.x) + (aC.x + aD.x),
                       (aA.y + aB.y) + (aC.y + aD.y));
}

// ---------------- agg1 + fused GEMM2: Gb = relu(dis*agg+b1) @ W2 ---------------
__global__ void __launch_bounds__(256) k_agg1(const float* __restrict__ bias,
                                              const float* __restrict__ W2) {
    __shared__ float2 sw2[HIDDEN * 32];      // 16 KB
    __shared__ float  sh[8][HIDDEN];         // 2 KB
    int tid = threadIdx.x;
    for (int i = tid; i < HIDDEN * 32; i += 256) sw2[i] = ((const float2*)W2)[i];
    __syncthreads();
    int w = tid >> 5, lane = tid & 31;
    int node = blockIdx.x * 8 + w;
    float2 acc = agg_node(d_ga, node, lane);
    float s = d_dis[node];
    float2 bb = ((const float2*)bias)[lane];
    sh[w][2 * lane]     = fmaxf(s * acc.x + bb.x, 0.f);
    sh[w][2 * lane + 1] = fmaxf(s * acc.y + bb.y, 0.f);
    __syncwarp();
    float2 o = make_float2(0.f, 0.f);
#pragma unroll
    for (int k = 0; k < HIDDEN; k++) {
        float hk = sh[w][k];
        float2 wv = sw2[k * 32 + lane];
        o.x += hk * wv.x;
        o.y += hk * wv.y;
    }
    d_gb[node * 32 + lane] = o;              // unscaled; dis applied at gather
}

// ---------------- agg2 + pooled RED --------------------------------------------
__global__ void __launch_bounds__(256) k_agg2(const float* __restrict__ bias) {
    int tid = threadIdx.x;
    int w = tid >> 5, lane = tid & 31;
    int node = blockIdx.x * 8 + w;
    float2 acc = agg_node(d_gb, node, lane);
    float s = d_dis[node];
    float2 bb = ((const float2*)bias)[lane];
    float rx = fmaxf(s * acc.x + bb.x, 0.f);
    float ry = fmaxf(s * acc.y + bb.y, 0.f);
    int b = d_batch[node];
    float* p = &d_pool[b * HIDDEN + lane * 2];
    asm volatile("red.global.add.v2.f32 [%0], {%1, %2};"
                 :: "l"(p), "f"(rx), "f"(ry) : "memory");
}

// ---------------- MLP head ------------------------------------------------------
__global__ void k_mlp(const float* __restrict__ Wm1, const float* __restrict__ bm1,
                      const float* __restrict__ Wm2, const float* __restrict__ bm2,
                      float* __restrict__ out) {
    __shared__ float sp[HIDDEN];
    __shared__ float sred[HIDDEN];
    int g = blockIdx.x, j = threadIdx.x;
    float inv = 1.0f / fmaxf(d_cnt[g], 1.0f);
    sp[j] = d_pool[g * HIDDEN + j] * inv;
    __syncthreads();
    float acc = bm1[j];
#pragma unroll
    for (int k = 0; k < HIDDEN; k++) acc += sp[k] * Wm1[k * HIDDEN + j];
    float v = fmaxf(acc, 0.f) * Wm2[j];
    sred[j] = v;
    __syncthreads();
    if (j < 32) {
        float t = sred[j] + sred[j + 32];
        for (int o = 16; o; o >>= 1) t += __shfl_down_sync(0xffffffff, t, o);
        if (j == 0) out[g] = t + bm2[0];
    }
}

// ---------------- launch --------------------------------------------------------
extern "C" void kernel_launch(void* const* d_in, const int* in_sizes, int n_in,
                              void* d_out, int out_size) {
    const float* x   = (const float*)d_in[0];
    const void*  ei  = d_in[1];
    const void*  bt  = d_in[2];
    const float* W1  = (const float*)d_in[3];
    const float* b1  = (const float*)d_in[4];
    const float* W2  = (const float*)d_in[5];
    const float* b2  = (const float*)d_in[6];
    const float* Wm1 = (const float*)d_in[7];
    const float* bm1 = (const float*)d_in[8];
    const float* Wm2 = (const float*)d_in[9];
    const float* bm2 = (const float*)d_in[10];
    float* out = (float*)d_out;

    k_prep<<<200, 256>>>((const int*)ei);
    k_convert<<<(N_EDGES / 4 + 255) / 256, 256>>>(ei, bt);
    k_scan<<<NB_SCAN, 256>>>();
    k_fill_gemm<<<NB_GEMM + NB_FILL, 256>>>(x, W1);

    k_agg1<<<N_NODES / 8, 256>>>(b1, W2);
    k_agg2<<<N_NODES / 8, 256>>>(b2);

    k_mlp<<<N_GRAPHS, HIDDEN>>>(Wm1, bm1, Wm2, bm2, out);
}

// round 6
// speedup vs baseline: 1.0045x; 1.0045x over previous
#include <cuda_runtime.h>
#include <cuda_bf16.h>
#include <cstdint>

#define N_NODES   50000
#define N_EDGES   800000
#define N_FEAT    128
#define HIDDEN    64
#define N_GRAPHS  256
#define NB_SCAN   196               // 196*256 = 50176 >= N_NODES
#define NB_GEMM   782               // ceil(50000/64)
#define NB_FILL   782               // ceil(800000/4/256)

// ---------------- scratch ----------------------------------------------------
__device__ __align__(16) int    d_src[N_EDGES];
__device__ __align__(16) int    d_dst[N_EDGES];
__device__ __align__(16) int    d_csr_src[N_EDGES];
__device__ int    d_batch[N_NODES];
__device__ int    d_flag;
__device__ int    d_ecnt[N_NODES];
__device__ int    d_ptr[N_NODES];
__device__ int    d_cur[N_NODES];
__device__ int    d_bagg[NB_SCAN];
__device__ int    d_binc[NB_SCAN];
__device__ int    d_bflag[NB_SCAN];
__device__ float  d_dis[N_NODES];
__device__ __align__(16) float2 d_ga[(N_NODES + 1) * 32];  // dis*(x@W1) + zero row
__device__ __align__(16) float2 d_gb[(N_NODES + 1) * 32];  // dis*(h@W2) + zero row
__device__ float  d_pool[N_GRAPHS * HIDDEN];
__device__ float  d_cnt[N_GRAPHS];

// ---------------- prep: zero scratch + dtype flag ------------------------------
__global__ void k_prep(const int* __restrict__ ebuf) {
    int i = blockIdx.x * blockDim.x + threadIdx.x;
    if (i < N_NODES) d_ecnt[i] = 0;
    if (i < N_GRAPHS * HIDDEN) d_pool[i] = 0.f;
    if (i < N_GRAPHS) d_cnt[i] = 0.f;
    if (i < NB_SCAN) d_bflag[i] = 0;
    if (i < 32) {
        d_ga[N_NODES * 32 + i] = make_float2(0.f, 0.f);
        d_gb[N_NODES * 32 + i] = make_float2(0.f, 0.f);
    }
    if (blockIdx.x == 0) {
        __shared__ int ok;
        if (threadIdx.x == 0) ok = 1;
        __syncthreads();
        int bad = 0;
        for (int t = threadIdx.x; t < 1024; t += blockDim.x)
            if (ebuf[2 * t + 1] != 0) bad = 1;
        if (bad) ok = 0;
        __syncthreads();
        if (threadIdx.x == 0) d_flag = ok;
    }
}

// ---------------- convert (4 edges/thread) + histogram + batch -----------------
__global__ void k_convert(const void* __restrict__ e, const void* __restrict__ b) {
    int t = blockIdx.x * blockDim.x + threadIdx.x;
    int f = d_flag;
    int e0 = t * 4;
    if (e0 < N_EDGES) {
        int s[4], dd[4];
        if (f) {
            const long long* p = (const long long*)e;
#pragma unroll
            for (int k = 0; k < 4; k++) { s[k] = (int)p[e0 + k]; dd[k] = (int)p[e0 + k + N_EDGES]; }
        } else {
            const int* p = (const int*)e;
#pragma unroll
            for (int k = 0; k < 4; k++) { s[k] = p[e0 + k]; dd[k] = p[e0 + k + N_EDGES]; }
        }
        ((int4*)d_src)[t] = make_int4(s[0], s[1], s[2], s[3]);
        ((int4*)d_dst)[t] = make_int4(dd[0], dd[1], dd[2], dd[3]);
#pragma unroll
        for (int k = 0; k < 4; k++) atomicAdd(&d_ecnt[dd[k]], 1);
    }
    if (t < N_NODES) {
        int bb = f ? (int)((const long long*)b)[t] : ((const int*)b)[t];
        d_batch[t] = bb;
        atomicAdd(&d_cnt[bb], 1.0f);
    }
}

// ---------------- single-pass scan (decoupled lookback) ------------------------
__global__ void __launch_bounds__(256) k_scan() {
    __shared__ int sm[256];
    __shared__ int s_exc;
    int t = threadIdx.x, bid = blockIdx.x;
    int i = bid * 256 + t;
    int v = (i < N_NODES) ? d_ecnt[i] : 0;
    sm[t] = v;
    __syncthreads();
    for (int off = 1; off < 256; off <<= 1) {
        int u = (t >= off) ? sm[t - off] : 0;
        __syncthreads();
        sm[t] += u;
        __syncthreads();
    }
    int incl = sm[t];
    int total = sm[255];
    if (t == 0) {
        d_bagg[bid] = total;
        __threadfence();
        d_bflag[bid] = 1;
    }
    if (t < 32) {
        int sum = 0;
        int pos = bid - 1;
        while (pos >= 0) {
            int p = pos - t;
            int fl = 0, val = 0;
            if (p >= 0) {
                do { fl = ((volatile int*)d_bflag)[p]; } while (fl == 0);
                val = (fl == 2) ? ((volatile int*)d_binc)[p]
                                : ((volatile int*)d_bagg)[p];
            }
            unsigned ball = __ballot_sync(0xffffffffu, fl == 2 && p >= 0);
            if (ball) {
                int lead = __ffs(ball) - 1;
                sum += (t <= lead) ? val : 0;
                pos = -1;
            } else {
                sum += (p >= 0) ? val : 0;
                pos -= 32;
            }
        }
        for (int o = 16; o; o >>= 1) sum += __shfl_down_sync(0xffffffffu, sum, o);
        if (t == 0) {
            s_exc = sum;
            d_binc[bid] = sum + total;
            __threadfence();
            d_bflag[bid] = 2;
        }
    }
    __syncthreads();
    if (i < N_NODES) {
        int p = s_exc + incl - v;
        d_ptr[i] = p;
        d_cur[i] = p;
        d_dis[i] = rsqrtf((float)(v + 1));
    }
}

// ---------------- fat kernel: interleaved gemm1 + fill blocks ------------------
// even bid -> gemm (Ga = dis * (X @ W1), X streamed via L1 broadcast)
// odd  bid -> fill (csr_src[pos] = src)
__global__ void __launch_bounds__(256) k_fill_gemm(const float* __restrict__ X,
                                                   const float* __restrict__ W) {
    __shared__ float4 sw[N_FEAT * 16];       // 32 KB only
    int tid = threadIdx.x;
    if (blockIdx.x & 1) {
        // ----- fill part -----
        int t = (blockIdx.x >> 1) * 256 + tid;
        int e0 = t * 4;
        if (e0 >= N_EDGES) return;
        int4 s4 = ((const int4*)d_src)[t];
        int4 d4 = ((const int4*)d_dst)[t];
        int p0 = atomicAdd(&d_cur[d4.x], 1);
        int p1 = atomicAdd(&d_cur[d4.y], 1);
        int p2 = atomicAdd(&d_cur[d4.z], 1);
        int p3 = atomicAdd(&d_cur[d4.w], 1);
        d_csr_src[p0] = s4.x;
        d_csr_src[p1] = s4.y;
        d_csr_src[p2] = s4.z;
        d_csr_src[p3] = s4.w;
        return;
    }
    // ----- gemm part -----
    int w = tid >> 5, lane = tid & 31, h = lane >> 4, l16 = lane & 15;
    for (int i = tid; i < N_FEAT * 16; i += 256) sw[i] = ((const float4*)W)[i];
    __syncthreads();
    int row0 = (blockIdx.x >> 1) * 64;
    int rbase = w * 8 + h * 4;
    const float4* X4 = (const float4*)X;
    // clamp rows for the tail block; stores are guarded below
    int r0 = min(row0 + rbase + 0, N_NODES - 1);
    int r1 = min(row0 + rbase + 1, N_NODES - 1);
    int r2 = min(row0 + rbase + 2, N_NODES - 1);
    int r3 = min(row0 + rbase + 3, N_NODES - 1);
    float4 acc[4] = {{0,0,0,0},{0,0,0,0},{0,0,0,0},{0,0,0,0}};
    for (int k = 0; k < N_FEAT; k += 4) {
        int kq = k >> 2;
        float4 xr[4];
        xr[0] = __ldg(&X4[r0 * 32 + kq]);
        xr[1] = __ldg(&X4[r1 * 32 + kq]);
        xr[2] = __ldg(&X4[r2 * 32 + kq]);
        xr[3] = __ldg(&X4[r3 * 32 + kq]);
        float4 w0 = sw[(k + 0) * 16 + l16];
        float4 w1 = sw[(k + 1) * 16 + l16];
        float4 w2 = sw[(k + 2) * 16 + l16];
        float4 w3 = sw[(k + 3) * 16 + l16];
#pragma unroll
        for (int r = 0; r < 4; r++) {
            float4 xv = xr[r];
            acc[r].x += xv.x * w0.x + xv.y * w1.x + xv.z * w2.x + xv.w * w3.x;
            acc[r].y += xv.x * w0.y + xv.y * w1.y + xv.z * w2.y + xv.w * w3.y;
            acc[r].z += xv.x * w0.z + xv.y * w1.z + xv.z * w2.z + xv.w * w3.z;
            acc[r].w += xv.x * w0.w + xv.y * w1.w + xv.z * w2.w + xv.w * w3.w;
        }
    }
#pragma unroll
    for (int r = 0; r < 4; r++) {
        int row = row0 + rbase + r;
        if (row < N_NODES) {
            float s = d_dis[row];
            float4 v = acc[r];
            ((float4*)d_ga)[row * 16 + l16] = make_float4(v.x*s, v.y*s, v.z*s, v.w*s);
        }
    }
}

// ---------------- CSR gather (full warp float2, unroll 16, 4 accs) -------------
__device__ __forceinline__ float2 agg_node(const float2* __restrict__ g2,
                                           int node, int lane) {
    int start = d_ptr[node];
    int n = d_ecnt[node];
    float2 aA = g2[node * 32 + lane];        // self-loop term (g already scaled)
    float2 aB = make_float2(0.f, 0.f);
    float2 aC = make_float2(0.f, 0.f);
    float2 aD = make_float2(0.f, 0.f);
    for (int base = 0; base < n; base += 32) {
        int rem = n - base;
        int idx = (lane < rem) ? d_csr_src[start + base + lane] : N_NODES;  // zero row
        int mm = rem < 32 ? rem : 32;
#pragma unroll 1
        for (int jj = 0; jj < mm; jj += 16) {
#pragma unroll
            for (int j = 0; j < 16; j++) {
                int s = __shfl_sync(0xffffffffu, idx, jj + j);
                float2 a = g2[s * 32 + lane];
                switch (j & 3) {
                    case 0:  aA.x += a.x; aA.y += a.y; break;
                    case 1:  aB.x += a.x; aB.y += a.y; break;
                    case 2:  aC.x += a.x; aC.y += a.y; break;
                    default: aD.x += a.x; aD.y += a.y; break;
                }
            }
        }
    }
    return make_float2((aA.x + aB.x) + (aC.x + aD.x),
                       (aA.y + aB.y) + (aC.y + aD.y));
}

// ---------------- agg1 + fused GEMM2: Gb = dis * (relu(dis*agg+b1) @ W2) -------
__global__ void __launch_bounds__(256) k_agg1(const float* __restrict__ bias,
                                              const float* __restrict__ W2) {
    __shared__ float2 sw2[HIDDEN * 32];      // 16 KB
    __shared__ float  sh[8][HIDDEN];         // 2 KB
    int tid = threadIdx.x;
    for (int i = tid; i < HIDDEN * 32; i += 256) sw2[i] = ((const float2*)W2)[i];
    __syncthreads();
    int w = tid >> 5, lane = tid & 31;
    int node = blockIdx.x * 8 + w;
    float2 acc = agg_node(d_ga, node, lane);
    float s = d_dis[node];
    float2 bb = ((const float2*)bias)[lane];
    sh[w][2 * lane]     = fmaxf(s * acc.x + bb.x, 0.f);
    sh[w][2 * lane + 1] = fmaxf(s * acc.y + bb.y, 0.f);
    __syncwarp();
    float2 o = make_float2(0.f, 0.f);
#pragma unroll
    for (int k = 0; k < HIDDEN; k++) {
        float hk = sh[w][k];
        float2 wv = sw2[k * 32 + lane];
        o.x += hk * wv.x;
        o.y += hk * wv.y;
    }
    d_gb[node * 32 + lane] = make_float2(o.x * s, o.y * s);
}

// ---------------- agg2 + pooled RED --------------------------------------------
__global__ void __launch_bounds__(256) k_agg2(const float* __restrict__ bias) {
    int tid = threadIdx.x;
    int w = tid >> 5, lane = tid & 31;
    int node = blockIdx.x * 8 + w;
    float2 acc = agg_node(d_gb, node, lane);
    float s = d_dis[node];
    float2 bb = ((const float2*)bias)[lane];
    float rx = fmaxf(s * acc.x + bb.x, 0.f);
    float ry = fmaxf(s * acc.y + bb.y, 0.f);
    int b = d_batch[node];
    float* p = &d_pool[b * HIDDEN + lane * 2];
    asm volatile("red.global.add.v2.f32 [%0], {%1, %2};"
                 :: "l"(p), "f"(rx), "f"(ry) : "memory");
}

// ---------------- MLP head ------------------------------------------------------
__global__ void k_mlp(const float* __restrict__ Wm1, const float* __restrict__ bm1,
                      const float* __restrict__ Wm2, const float* __restrict__ bm2,
                      float* __restrict__ out) {
    __shared__ float sp[HIDDEN];
    __shared__ float sred[HIDDEN];
    int g = blockIdx.x, j = threadIdx.x;
    float inv = 1.0f / fmaxf(d_cnt[g], 1.0f);
    sp[j] = d_pool[g * HIDDEN + j] * inv;
    __syncthreads();
    float acc = bm1[j];
#pragma unroll
    for (int k = 0; k < HIDDEN; k++) acc += sp[k] * Wm1[k * HIDDEN + j];
    float v = fmaxf(acc, 0.f) * Wm2[j];
    sred[j] = v;
    __syncthreads();
    if (j < 32) {
        float t = sred[j] + sred[j + 32];
        for (int o = 16; o; o >>= 1) t += __shfl_down_sync(0xffffffff, t, o);
        if (j == 0) out[g] = t + bm2[0];
    }
}

// ---------------- launch --------------------------------------------------------
extern "C" void kernel_launch(void* const* d_in, const int* in_sizes, int n_in,
                              void* d_out, int out_size) {
    const float* x   = (const float*)d_in[0];
    const void*  ei  = d_in[1];
    const void*  bt  = d_in[2];
    const float* W1  = (const float*)d_in[3];
    const float* b1  = (const float*)d_in[4];
    const float* W2  = (const float*)d_in[5];
    const float* b2  = (const float*)d_in[6];
    const float* Wm1 = (const float*)d_in[7];
    const float* bm1 = (const float*)d_in[8];
    const float* Wm2 = (const float*)d_in[9];
    const float* bm2 = (const float*)d_in[10];
    float* out = (float*)d_out;

    k_prep<<<200, 256>>>((const int*)ei);
    k_convert<<<(N_EDGES / 4 + 255) / 256, 256>>>(ei, bt);
    k_scan<<<NB_SCAN, 256>>>();
    k_fill_gemm<<<NB_GEMM + NB_FILL, 256>>>(x, W1);

    k_agg1<<<N_NODES / 8, 256>>>(b1, W2);
    k_agg2<<<N_NODES / 8, 256>>>(b2);

    k_mlp<<<N_GRAPHS, HIDDEN>>>(Wm1, bm1, Wm2, bm2, out);
}

// round 7
// speedup vs baseline: 1.1705x; 1.1653x over previous
#include <cuda_runtime.h>
#include <cuda_bf16.h>
#include <cstdint>

#define N_NODES   50000
#define N_EDGES   800000
#define N_FEAT    128
#define HIDDEN    64
#define N_GRAPHS  256
#define NB_SCAN   196               // 196*256 = 50176 >= N_NODES
#define NB_CONV   391               // ceil(800000/8/256); also covers 50000 batch
#define NB_GEMM   782               // ceil(50000/64)

typedef unsigned long long u64;

// ---------------- f32x2 packed helpers (Blackwell) -----------------------------
__device__ __forceinline__ u64 f2pack(float lo, float hi) {
    u64 r;
    asm("mov.b64 %0, {%1, %2};" : "=l"(r) : "f"(lo), "f"(hi));
    return r;
}
__device__ __forceinline__ void ffma2(u64& d, u64 a, u64 b) {
    asm("fma.rn.f32x2 %0, %1, %2, %0;" : "+l"(d) : "l"(a), "l"(b));
}
__device__ __forceinline__ float2 f2unpack(u64 v) {
    float2 r;
    asm("mov.b64 {%0, %1}, %2;" : "=f"(r.x), "=f"(r.y) : "l"(v));
    return r;
}

// ---------------- scratch ----------------------------------------------------
__device__ __align__(16) int    d_src[N_EDGES];
__device__ __align__(16) int    d_dst[N_EDGES];
__device__ __align__(16) int    d_rank[N_EDGES];   // rank of edge within its dst
__device__ __align__(16) int    d_csr_src[N_EDGES];
__device__ int    d_batch[N_NODES];
__device__ int    d_flag;
__device__ int    d_ecnt[N_NODES];
__device__ int    d_ptr[N_NODES];
__device__ int    d_bagg[NB_SCAN];
__device__ int    d_binc[NB_SCAN];
__device__ int    d_bflag[NB_SCAN];
__device__ float  d_dis[N_NODES];
__device__ __align__(16) float2 d_ga[(N_NODES + 1) * 32];  // dis*(x@W1) + zero row
__device__ __align__(16) float2 d_gb[(N_NODES + 1) * 32];  // dis*(h@W2) + zero row
__device__ float  d_pool[N_GRAPHS * HIDDEN];
__device__ float  d_cnt[N_GRAPHS];

// ---------------- prep: zero scratch + dtype flag ------------------------------
__global__ void k_prep(const int* __restrict__ ebuf) {
    int i = blockIdx.x * blockDim.x + threadIdx.x;
    if (i < N_NODES) d_ecnt[i] = 0;
    if (i < N_GRAPHS * HIDDEN) d_pool[i] = 0.f;
    if (i < N_GRAPHS) d_cnt[i] = 0.f;
    if (i < NB_SCAN) d_bflag[i] = 0;
    if (i < 32) {
        d_ga[N_NODES * 32 + i] = make_float2(0.f, 0.f);
        d_gb[N_NODES * 32 + i] = make_float2(0.f, 0.f);
    }
    if (blockIdx.x == 0) {
        __shared__ int ok;
        if (threadIdx.x == 0) ok = 1;
        __syncthreads();
        int bad = 0;
        for (int t = threadIdx.x; t < 1024; t += blockDim.x)
            if (ebuf[2 * t + 1] != 0) bad = 1;
        if (bad) ok = 0;
        __syncthreads();
        if (threadIdx.x == 0) d_flag = ok;
    }
}

// ---------------- convert (8 edges/thread) + histogram ranks + batch -----------
__global__ void k_convert(const void* __restrict__ e, const void* __restrict__ b) {
    int t = blockIdx.x * blockDim.x + threadIdx.x;
    int f = d_flag;
    int e0 = t * 8;
    if (e0 < N_EDGES) {                        // N_EDGES % 8 == 0
        int s[8], dd[8], r[8];
        if (f) {
            const long long* p = (const long long*)e;
#pragma unroll
            for (int k = 0; k < 8; k++) { s[k] = (int)p[e0 + k]; dd[k] = (int)p[e0 + k + N_EDGES]; }
        } else {
            const int* p = (const int*)e;
#pragma unroll
            for (int k = 0; k < 8; k++) { s[k] = p[e0 + k]; dd[k] = p[e0 + k + N_EDGES]; }
        }
        ((int4*)d_src)[2 * t]     = make_int4(s[0], s[1], s[2], s[3]);
        ((int4*)d_src)[2 * t + 1] = make_int4(s[4], s[5], s[6], s[7]);
        ((int4*)d_dst)[2 * t]     = make_int4(dd[0], dd[1], dd[2], dd[3]);
        ((int4*)d_dst)[2 * t + 1] = make_int4(dd[4], dd[5], dd[6], dd[7]);
#pragma unroll
        for (int k = 0; k < 8; k++) r[k] = atomicAdd(&d_ecnt[dd[k]], 1);
        ((int4*)d_rank)[2 * t]     = make_int4(r[0], r[1], r[2], r[3]);
        ((int4*)d_rank)[2 * t + 1] = make_int4(r[4], r[5], r[6], r[7]);
    }
    if (t < N_NODES) {
        int bb = f ? (int)((const long long*)b)[t] : ((const int*)b)[t];
        d_batch[t] = bb;
        atomicAdd(&d_cnt[bb], 1.0f);
    }
}

// ---------------- single-pass scan (decoupled lookback) ------------------------
__global__ void __launch_bounds__(256) k_scan() {
    __shared__ int sm[256];
    __shared__ int s_exc;
    int t = threadIdx.x, bid = blockIdx.x;
    int i = bid * 256 + t;
    int v = (i < N_NODES) ? d_ecnt[i] : 0;
    sm[t] = v;
    __syncthreads();
    for (int off = 1; off < 256; off <<= 1) {
        int u = (t >= off) ? sm[t - off] : 0;
        __syncthreads();
        sm[t] += u;
        __syncthreads();
    }
    int incl = sm[t];
    int total = sm[255];
    if (t == 0) {
        d_bagg[bid] = total;
        __threadfence();
        d_bflag[bid] = 1;
    }
    if (t < 32) {
        int sum = 0;
        int pos = bid - 1;
        while (pos >= 0) {
            int p = pos - t;
            int fl = 0, val = 0;
            if (p >= 0) {
                do { fl = ((volatile int*)d_bflag)[p]; } while (fl == 0);
                val = (fl == 2) ? ((volatile int*)d_binc)[p]
                                : ((volatile int*)d_bagg)[p];
            }
            unsigned ball = __ballot_sync(0xffffffffu, fl == 2 && p >= 0);
            if (ball) {
                int lead = __ffs(ball) - 1;
                sum += (t <= lead) ? val : 0;
                pos = -1;
            } else {
                sum += (p >= 0) ? val : 0;
                pos -= 32;
            }
        }
        for (int o = 16; o; o >>= 1) sum += __shfl_down_sync(0xffffffffu, sum, o);
        if (t == 0) {
            s_exc = sum;
            d_binc[bid] = sum + total;
            __threadfence();
            d_bflag[bid] = 2;
        }
    }
    __syncthreads();
    if (i < N_NODES) {
        d_ptr[i] = s_exc + incl - v;
        d_dis[i] = rsqrtf((float)(v + 1));
    }
}

// ---------------- CSR fill (no atomics: pos = ptr[dst] + rank) ------------------
__global__ void k_fill() {
    int t = blockIdx.x * blockDim.x + threadIdx.x;
    int e0 = t * 8;
    if (e0 >= N_EDGES) return;
    int4 sa = ((const int4*)d_src)[2 * t];
    int4 sb = ((const int4*)d_src)[2 * t + 1];
    int4 da = ((const int4*)d_dst)[2 * t];
    int4 db = ((const int4*)d_dst)[2 * t + 1];
    int4 ra = ((const int4*)d_rank)[2 * t];
    int4 rb = ((const int4*)d_rank)[2 * t + 1];
    int s[8]  = {sa.x, sa.y, sa.z, sa.w, sb.x, sb.y, sb.z, sb.w};
    int dd[8] = {da.x, da.y, da.z, da.w, db.x, db.y, db.z, db.w};
    int rr[8] = {ra.x, ra.y, ra.z, ra.w, rb.x, rb.y, rb.z, rb.w};
    int p[8];
#pragma unroll
    for (int k = 0; k < 8; k++) p[k] = d_ptr[dd[k]] + rr[k];
#pragma unroll
    for (int k = 0; k < 8; k++) d_csr_src[p[k]] = s[k];
}

// ---------------- GEMM1: Ga = dis * (X @ W1), f32x2 ----------------------------
__global__ void __launch_bounds__(256) k_gemm1(const float* __restrict__ X,
                                               const float* __restrict__ W) {
    __shared__ float4 sw[N_FEAT * 16];       // 32 KB  [k][l16] -> 4 cols
    __shared__ float  sx[64][N_FEAT];        // 32 KB
    int tid = threadIdx.x;
    int w = tid >> 5, lane = tid & 31, h = lane >> 4, l16 = lane & 15;
    for (int i = tid; i < N_FEAT * 16; i += 256) sw[i] = ((const float4*)W)[i];
    int row0 = blockIdx.x * 64;
    const float4* X4 = (const float4*)X;
    for (int i = tid; i < 64 * 32; i += 256) {
        int r = i >> 5, c = i & 31;
        int row = row0 + r;
        float4 v = (row < N_NODES) ? X4[row * 32 + c] : make_float4(0.f, 0.f, 0.f, 0.f);
        ((float4*)&sx[r][0])[c] = v;
    }
    __syncthreads();
    int rbase = w * 8 + h * 4;
    u64 acc01[4], acc23[4];
#pragma unroll
    for (int r = 0; r < 4; r++) { acc01[r] = f2pack(0.f, 0.f); acc23[r] = f2pack(0.f, 0.f); }
    for (int k = 0; k < N_FEAT; k += 4) {
        float4 xq[4];
#pragma unroll
        for (int r = 0; r < 4; r++) xq[r] = *(const float4*)&sx[rbase + r][k];
#pragma unroll
        for (int kk = 0; kk < 4; kk++) {
            float4 wv = sw[(k + kk) * 16 + l16];
            u64 w01 = f2pack(wv.x, wv.y);
            u64 w23 = f2pack(wv.z, wv.w);
#pragma unroll
            for (int r = 0; r < 4; r++) {
                float xv = (kk == 0) ? xq[r].x : (kk == 1) ? xq[r].y
                         : (kk == 2) ? xq[r].z : xq[r].w;
                u64 xx = f2pack(xv, xv);
                ffma2(acc01[r], xx, w01);
                ffma2(acc23[r], xx, w23);
            }
        }
    }
#pragma unroll
    for (int r = 0; r < 4; r++) {
        int row = row0 + rbase + r;
        if (row < N_NODES) {
            float s = d_dis[row];
            float2 p01 = f2unpack(acc01[r]);
            float2 p23 = f2unpack(acc23[r]);
            ((float4*)d_ga)[row * 16 + l16] =
                make_float4(p01.x * s, p01.y * s, p23.x * s, p23.y * s);
        }
    }
}

// ---------------- CSR gather (full warp float2, unroll 16, 4 accs) -------------
__device__ __forceinline__ float2 agg_node(const float2* __restrict__ g2,
                                           int node, int lane) {
    int start = d_ptr[node];
    int n = d_ecnt[node];
    float2 aA = g2[node * 32 + lane];        // self-loop term (g already scaled)
    float2 aB = make_float2(0.f, 0.f);
    float2 aC = make_float2(0.f, 0.f);
    float2 aD = make_float2(0.f, 0.f);
    for (int base = 0; base < n; base += 32) {
        int rem = n - base;
        int idx = (lane < rem) ? d_csr_src[start + base + lane] : N_NODES;  // zero row
        int mm = rem < 32 ? rem : 32;
#pragma unroll 1
        for (int jj = 0; jj < mm; jj += 16) {
#pragma unroll
            for (int j = 0; j < 16; j++) {
                int s = __shfl_sync(0xffffffffu, idx, jj + j);
                float2 a = g2[s * 32 + lane];
                switch (j & 3) {
                    case 0:  aA.x += a.x; aA.y += a.y; break;
                    case 1:  aB.x += a.x; aB.y += a.y; break;
                    case 2:  aC.x += a.x; aC.y += a.y; break;
                    default: aD.x += a.x; aD.y += a.y; break;
                }
            }
        }
    }
    return make_float2((aA.x + aB.x) + (aC.x + aD.x),
                       (aA.y + aB.y) + (aC.y + aD.y));
}

// ---------------- agg1 + fused GEMM2 (2 nodes/warp share W2 loads) -------------
__global__ void __launch_bounds__(256) k_agg1(const float* __restrict__ bias,
                                              const float* __restrict__ W2) {
    __shared__ u64   sw2[HIDDEN * 32];       // 16 KB  [k][lane] -> col pair
    __shared__ float sh[16][HIDDEN];         // 4 KB
    int tid = threadIdx.x;
    const u64* W2u = (const u64*)W2;
    for (int i = tid; i < HIDDEN * 32; i += 256) sw2[i] = W2u[i];
    __syncthreads();
    int w = tid >> 5, lane = tid & 31;
    int nodeA = blockIdx.x * 16 + 2 * w;
    int nodeB = nodeA + 1;
    float2 accA = agg_node(d_ga, nodeA, lane);
    float2 accB = agg_node(d_ga, nodeB, lane);
    float sA = d_dis[nodeA], sB = d_dis[nodeB];
    float2 bb = ((const float2*)bias)[lane];
    float2 hA = make_float2(fmaxf(sA * accA.x + bb.x, 0.f),
                            fmaxf(sA * accA.y + bb.y, 0.f));
    float2 hB = make_float2(fmaxf(sB * accB.x + bb.x, 0.f),
                            fmaxf(sB * accB.y + bb.y, 0.f));
    ((float2*)&sh[2 * w][0])[lane]     = hA;
    ((float2*)&sh[2 * w + 1][0])[lane] = hB;
    __syncwarp();
    u64 oA = f2pack(0.f, 0.f), oB = f2pack(0.f, 0.f);
#pragma unroll 16
    for (int k = 0; k < HIDDEN; k++) {
        u64 wv = sw2[k * 32 + lane];
        ffma2(oA, f2pack(sh[2 * w][k],     sh[2 * w][k]),     wv);
        ffma2(oB, f2pack(sh[2 * w + 1][k], sh[2 * w + 1][k]), wv);
    }
    float2 a = f2unpack(oA), b = f2unpack(oB);
    d_gb[nodeA * 32 + lane] = make_float2(a.x * sA, a.y * sA);
    d_gb[nodeB * 32 + lane] = make_float2(b.x * sB, b.y * sB);
}

// ---------------- agg2 + pooled RED --------------------------------------------
__global__ void __launch_bounds__(256) k_agg2(const float* __restrict__ bias) {
    int tid = threadIdx.x;
    int w = tid >> 5, lane = tid & 31;
    int node = blockIdx.x * 8 + w;
    float2 acc = agg_node(d_gb, node, lane);
    float s = d_dis[node];
    float2 bb = ((const float2*)bias)[lane];
    float rx = fmaxf(s * acc.x + bb.x, 0.f);
    float ry = fmaxf(s * acc.y + bb.y, 0.f);
    int b = d_batch[node];
    float* p = &d_pool[b * HIDDEN + lane * 2];
    asm volatile("red.global.add.v2.f32 [%0], {%1, %2};"
                 :: "l"(p), "f"(rx), "f"(ry) : "memory");
}

// ---------------- MLP head ------------------------------------------------------
__global__ void k_mlp(const float* __restrict__ Wm1, const float* __restrict__ bm1,
                      const float* __restrict__ Wm2, const float* __restrict__ bm2,
                      float* __restrict__ out) {
    __shared__ float sp[HIDDEN];
    __shared__ float sred[HIDDEN];
    int g = blockIdx.x, j = threadIdx.x;
    float inv = 1.0f / fmaxf(d_cnt[g], 1.0f);
    sp[j] = d_pool[g * HIDDEN + j] * inv;
    __syncthreads();
    float acc = bm1[j];
#pragma unroll
    for (int k = 0; k < HIDDEN; k++) acc += sp[k] * Wm1[k * HIDDEN + j];
    float v = fmaxf(acc, 0.f) * Wm2[j];
    sred[j] = v;
    __syncthreads();
    if (j < 32) {
        float t = sred[j] + sred[j + 32];
        for (int o = 16; o; o >>= 1) t += __shfl_down_sync(0xffffffff, t, o);
        if (j == 0) out[g] = t + bm2[0];
    }
}

// ---------------- launch --------------------------------------------------------
extern "C" void kernel_launch(void* const* d_in, const int* in_sizes, int n_in,
                              void* d_out, int out_size) {
    const float* x   = (const float*)d_in[0];
    const void*  ei  = d_in[1];
    const void*  bt  = d_in[2];
    const float* W1  = (const float*)d_in[3];
    const float* b1  = (const float*)d_in[4];
    const float* W2  = (const float*)d_in[5];
    const float* b2  = (const float*)d_in[6];
    const float* Wm1 = (const float*)d_in[7];
    const float* bm1 = (const float*)d_in[8];
    const float* Wm2 = (const float*)d_in[9];
    const float* bm2 = (const float*)d_in[10];
    float* out = (float*)d_out;

    k_prep<<<200, 256>>>((const int*)ei);
    k_convert<<<NB_CONV, 256>>>(ei, bt);
    k_scan<<<NB_SCAN, 256>>>();
    k_fill<<<NB_CONV, 256>>>();

    k_gemm1<<<NB_GEMM, 256>>>(x, W1);
    k_agg1<<<N_NODES / 16, 256>>>(b1, W2);
    k_agg2<<<N_NODES / 8, 256>>>(b2);

    k_mlp<<<N_GRAPHS, HIDDEN>>>(Wm1, bm1, Wm2, bm2, out);
}

// round 8
// speedup vs baseline: 1.3162x; 1.1244x over previous
#include <cuda_runtime.h>
#include <cuda_bf16.h>
#include <cstdint>

#define N_NODES   50000
#define N_EDGES   800000
#define N_FEAT    128
#define HIDDEN    64
#define N_GRAPHS  256
#define NB_SCAN   196               // 196*256 = 50176 >= N_NODES
#define NB_CONV   391               // ceil(800000/8/256); also covers 50000 batch
#define NB_GEMM   782               // ceil(50000/64)

typedef unsigned long long u64;

// ---------------- f32x2 packed helpers (Blackwell) -----------------------------
__device__ __forceinline__ u64 f2pack(float lo, float hi) {
    u64 r;
    asm("mov.b64 %0, {%1, %2};" : "=l"(r) : "f"(lo), "f"(hi));
    return r;
}
__device__ __forceinline__ void ffma2(u64& d, u64 a, u64 b) {
    asm("fma.rn.f32x2 %0, %1, %2, %0;" : "+l"(d) : "l"(a), "l"(b));
}
__device__ __forceinline__ float2 f2unpack(u64 v) {
    float2 r;
    asm("mov.b64 {%0, %1}, %2;" : "=f"(r.x), "=f"(r.y) : "l"(v));
    return r;
}

// ---------------- scratch ----------------------------------------------------
__device__ __align__(16) int    d_src[N_EDGES];
__device__ __align__(16) int    d_dst[N_EDGES];
__device__ __align__(16) int    d_rank[N_EDGES];   // rank of edge within its dst
__device__ __align__(16) int    d_csr_src[N_EDGES];
__device__ int    d_batch[N_NODES];
__device__ int    d_flag;
__device__ int    d_ecnt[N_NODES];
__device__ int    d_ptr[N_NODES];
__device__ int    d_bagg[NB_SCAN];
__device__ int    d_binc[NB_SCAN];
__device__ int    d_bflag[NB_SCAN];
__device__ float  d_dis[N_NODES];
__device__ __align__(16) float2 d_ga[(N_NODES + 1) * 32];  // dis*(x@W1) + zero row
__device__ __align__(16) float2 d_gb[(N_NODES + 1) * 32];  // dis*(h@W2) + zero row
__device__ float  d_pool[N_GRAPHS * HIDDEN];
__device__ float  d_cnt[N_GRAPHS];

// ---------------- prep: zero scratch + dtype flag ------------------------------
__global__ void k_prep(const int* __restrict__ ebuf) {
    int i = blockIdx.x * blockDim.x + threadIdx.x;
    if (i < N_NODES) d_ecnt[i] = 0;
    if (i < N_GRAPHS * HIDDEN) d_pool[i] = 0.f;
    if (i < N_GRAPHS) d_cnt[i] = 0.f;
    if (i < NB_SCAN) d_bflag[i] = 0;
    if (i < 32) {
        d_ga[N_NODES * 32 + i] = make_float2(0.f, 0.f);
        d_gb[N_NODES * 32 + i] = make_float2(0.f, 0.f);
    }
    if (blockIdx.x == 0) {
        __shared__ int ok;
        if (threadIdx.x == 0) ok = 1;
        __syncthreads();
        int bad = 0;
        for (int t = threadIdx.x; t < 1024; t += blockDim.x)
            if (ebuf[2 * t + 1] != 0) bad = 1;
        if (bad) ok = 0;
        __syncthreads();
        if (threadIdx.x == 0) d_flag = ok;
    }
}

// ---------------- convert (8 edges/thread) + histogram ranks + batch -----------
__global__ void k_convert(const void* __restrict__ e, const void* __restrict__ b) {
    int t = blockIdx.x * blockDim.x + threadIdx.x;
    int f = d_flag;
    int e0 = t * 8;
    if (e0 < N_EDGES) {                        // N_EDGES % 8 == 0
        int s[8], dd[8], r[8];
        if (f) {
            const long long* p = (const long long*)e;
#pragma unroll
            for (int k = 0; k < 8; k++) { s[k] = (int)p[e0 + k]; dd[k] = (int)p[e0 + k + N_EDGES]; }
        } else {
            const int* p = (const int*)e;
#pragma unroll
            for (int k = 0; k < 8; k++) { s[k] = p[e0 + k]; dd[k] = p[e0 + k + N_EDGES]; }
        }
        ((int4*)d_src)[2 * t]     = make_int4(s[0], s[1], s[2], s[3]);
        ((int4*)d_src)[2 * t + 1] = make_int4(s[4], s[5], s[6], s[7]);
        ((int4*)d_dst)[2 * t]     = make_int4(dd[0], dd[1], dd[2], dd[3]);
        ((int4*)d_dst)[2 * t + 1] = make_int4(dd[4], dd[5], dd[6], dd[7]);
#pragma unroll
        for (int k = 0; k < 8; k++) r[k] = atomicAdd(&d_ecnt[dd[k]], 1);
        ((int4*)d_rank)[2 * t]     = make_int4(r[0], r[1], r[2], r[3]);
        ((int4*)d_rank)[2 * t + 1] = make_int4(r[4], r[5], r[6], r[7]);
    }
    if (t < N_NODES) {
        int bb = f ? (int)((const long long*)b)[t] : ((const int*)b)[t];
        d_batch[t] = bb;
        // warp-aggregated count (batch is sorted -> heavy same-address sharing)
        unsigned am = __activemask();
        unsigned mask = __match_any_sync(am, bb);
        int leader = __ffs(mask) - 1;
        int lane = threadIdx.x & 31;
        if (lane == leader)
            atomicAdd(&d_cnt[bb], (float)__popc(mask));
    }
}

// ---------------- single-pass scan (decoupled lookback) ------------------------
__global__ void __launch_bounds__(256) k_scan() {
    __shared__ int sm[256];
    __shared__ int s_exc;
    int t = threadIdx.x, bid = blockIdx.x;
    int i = bid * 256 + t;
    int v = (i < N_NODES) ? d_ecnt[i] : 0;
    sm[t] = v;
    __syncthreads();
    for (int off = 1; off < 256; off <<= 1) {
        int u = (t >= off) ? sm[t - off] : 0;
        __syncthreads();
        sm[t] += u;
        __syncthreads();
    }
    int incl = sm[t];
    int total = sm[255];
    if (t == 0) {
        d_bagg[bid] = total;
        __threadfence();
        d_bflag[bid] = 1;
    }
    if (t < 32) {
        int sum = 0;
        int pos = bid - 1;
        while (pos >= 0) {
            int p = pos - t;
            int fl = 0, val = 0;
            if (p >= 0) {
                do { fl = ((volatile int*)d_bflag)[p]; } while (fl == 0);
                val = (fl == 2) ? ((volatile int*)d_binc)[p]
                                : ((volatile int*)d_bagg)[p];
            }
            unsigned ball = __ballot_sync(0xffffffffu, fl == 2 && p >= 0);
            if (ball) {
                int lead = __ffs(ball) - 1;
                sum += (t <= lead) ? val : 0;
                pos = -1;
            } else {
                sum += (p >= 0) ? val : 0;
                pos -= 32;
            }
        }
        for (int o = 16; o; o >>= 1) sum += __shfl_down_sync(0xffffffffu, sum, o);
        if (t == 0) {
            s_exc = sum;
            d_binc[bid] = sum + total;
            __threadfence();
            d_bflag[bid] = 2;
        }
    }
    __syncthreads();
    if (i < N_NODES) {
        d_ptr[i] = s_exc + incl - v;
        d_dis[i] = rsqrtf((float)(v + 1));
    }
}

// ---------------- CSR fill (no atomics: pos = ptr[dst] + rank) ------------------
__global__ void k_fill() {
    int t = blockIdx.x * blockDim.x + threadIdx.x;
    int e0 = t * 8;
    if (e0 >= N_EDGES) return;
    int4 sa = ((const int4*)d_src)[2 * t];
    int4 sb = ((const int4*)d_src)[2 * t + 1];
    int4 da = ((const int4*)d_dst)[2 * t];
    int4 db = ((const int4*)d_dst)[2 * t + 1];
    int4 ra = ((const int4*)d_rank)[2 * t];
    int4 rb = ((const int4*)d_rank)[2 * t + 1];
    int s[8]  = {sa.x, sa.y, sa.z, sa.w, sb.x, sb.y, sb.z, sb.w};
    int dd[8] = {da.x, da.y, da.z, da.w, db.x, db.y, db.z, db.w};
    int rr[8] = {ra.x, ra.y, ra.z, ra.w, rb.x, rb.y, rb.z, rb.w};
    int p[8];
#pragma unroll
    for (int k = 0; k < 8; k++) p[k] = d_ptr[dd[k]] + rr[k];
#pragma unroll
    for (int k = 0; k < 8; k++) d_csr_src[p[k]] = s[k];
}

// ---------------- GEMM1: Ga = dis * (X @ W1), f32x2 ----------------------------
__global__ void __launch_bounds__(256) k_gemm1(const float* __restrict__ X,
                                               const float* __restrict__ W) {
    __shared__ float4 sw[N_FEAT * 16];       // 32 KB  [k][l16] -> 4 cols
    __shared__ float  sx[64][N_FEAT];        // 32 KB
    int tid = threadIdx.x;
    int w = tid >> 5, lane = tid & 31, h = lane >> 4, l16 = lane & 15;
    for (int i = tid; i < N_FEAT * 16; i += 256) sw[i] = ((const float4*)W)[i];
    int row0 = blockIdx.x * 64;
    const float4* X4 = (const float4*)X;
    for (int i = tid; i < 64 * 32; i += 256) {
        int r = i >> 5, c = i & 31;
        int row = row0 + r;
        float4 v = (row < N_NODES) ? X4[row * 32 + c] : make_float4(0.f, 0.f, 0.f, 0.f);
        ((float4*)&sx[r][0])[c] = v;
    }
    __syncthreads();
    int rbase = w * 8 + h * 4;
    u64 acc01[4], acc23[4];
#pragma unroll
    for (int r = 0; r < 4; r++) { acc01[r] = f2pack(0.f, 0.f); acc23[r] = f2pack(0.f, 0.f); }
    for (int k = 0; k < N_FEAT; k += 4) {
        float4 xq[4];
#pragma unroll
        for (int r = 0; r < 4; r++) xq[r] = *(const float4*)&sx[rbase + r][k];
#pragma unroll
        for (int kk = 0; kk < 4; kk++) {
            float4 wv = sw[(k + kk) * 16 + l16];
            u64 w01 = f2pack(wv.x, wv.y);
            u64 w23 = f2pack(wv.z, wv.w);
#pragma unroll
            for (int r = 0; r < 4; r++) {
                float xv = (kk == 0) ? xq[r].x : (kk == 1) ? xq[r].y
                         : (kk == 2) ? xq[r].z : xq[r].w;
                u64 xx = f2pack(xv, xv);
                ffma2(acc01[r], xx, w01);
                ffma2(acc23[r], xx, w23);
            }
        }
    }
#pragma unroll
    for (int r = 0; r < 4; r++) {
        int row = row0 + rbase + r;
        if (row < N_NODES) {
            float s = d_dis[row];
            float2 p01 = f2unpack(acc01[r]);
            float2 p23 = f2unpack(acc23[r]);
            ((float4*)d_ga)[row * 16 + l16] =
                make_float4(p01.x * s, p01.y * s, p23.x * s, p23.y * s);
        }
    }
}

// ---------------- CSR gather (full warp float2, unroll 16, 4 accs) -------------
__device__ __forceinline__ float2 agg_node(const float2* __restrict__ g2,
                                           int node, int lane) {
    int start = d_ptr[node];
    int n = d_ecnt[node];
    float2 aA = g2[node * 32 + lane];        // self-loop term (g already scaled)
    float2 aB = make_float2(0.f, 0.f);
    float2 aC = make_float2(0.f, 0.f);
    float2 aD = make_float2(0.f, 0.f);
    for (int base = 0; base < n; base += 32) {
        int rem = n - base;
        int idx = (lane < rem) ? d_csr_src[start + base + lane] : N_NODES;  // zero row
        int mm = rem < 32 ? rem : 32;
#pragma unroll 1
        for (int jj = 0; jj < mm; jj += 16) {
#pragma unroll
            for (int j = 0; j < 16; j++) {
                int s = __shfl_sync(0xffffffffu, idx, jj + j);
                float2 a = g2[s * 32 + lane];
                switch (j & 3) {
                    case 0:  aA.x += a.x; aA.y += a.y; break;
                    case 1:  aB.x += a.x; aB.y += a.y; break;
                    case 2:  aC.x += a.x; aC.y += a.y; break;
                    default: aD.x += a.x; aD.y += a.y; break;
                }
            }
        }
    }
    return make_float2((aA.x + aB.x) + (aC.x + aD.x),
                       (aA.y + aB.y) + (aC.y + aD.y));
}

// ---------------- agg1 + fused GEMM2 (2 nodes/warp share W2 loads) -------------
__global__ void __launch_bounds__(256) k_agg1(const float* __restrict__ bias,
                                              const float* __restrict__ W2) {
    __shared__ u64   sw2[HIDDEN * 32];       // 16 KB  [k][lane] -> col pair
    __shared__ float sh[16][HIDDEN];         // 4 KB
    int tid = threadIdx.x;
    const u64* W2u = (const u64*)W2;
    for (int i = tid; i < HIDDEN * 32; i += 256) sw2[i] = W2u[i];
    __syncthreads();
    int w = tid >> 5, lane = tid & 31;
    int nodeA = blockIdx.x * 16 + 2 * w;
    int nodeB = nodeA + 1;
    float2 accA = agg_node(d_ga, nodeA, lane);
    float2 accB = agg_node(d_ga, nodeB, lane);
    float sA = d_dis[nodeA], sB = d_dis[nodeB];
    float2 bb = ((const float2*)bias)[lane];
    float2 hA = make_float2(fmaxf(sA * accA.x + bb.x, 0.f),
                            fmaxf(sA * accA.y + bb.y, 0.f));
    float2 hB = make_float2(fmaxf(sB * accB.x + bb.x, 0.f),
                            fmaxf(sB * accB.y + bb.y, 0.f));
    ((float2*)&sh[2 * w][0])[lane]     = hA;
    ((float2*)&sh[2 * w + 1][0])[lane] = hB;
    __syncwarp();
    u64 oA = f2pack(0.f, 0.f), oB = f2pack(0.f, 0.f);
#pragma unroll 16
    for (int k = 0; k < HIDDEN; k++) {
        u64 wv = sw2[k * 32 + lane];
        ffma2(oA, f2pack(sh[2 * w][k],     sh[2 * w][k]),     wv);
        ffma2(oB, f2pack(sh[2 * w + 1][k], sh[2 * w + 1][k]), wv);
    }
    float2 a = f2unpack(oA), b = f2unpack(oB);
    d_gb[nodeA * 32 + lane] = make_float2(a.x * sA, a.y * sA);
    d_gb[nodeB * 32 + lane] = make_float2(b.x * sB, b.y * sB);
}

// ---------------- agg2 + pooled RED --------------------------------------------
__global__ void __launch_bounds__(256) k_agg2(const float* __restrict__ bias) {
    int tid = threadIdx.x;
    int w = tid >> 5, lane = tid & 31;
    int node = blockIdx.x * 8 + w;
    float2 acc = agg_node(d_gb, node, lane);
    float s = d_dis[node];
    float2 bb = ((const float2*)bias)[lane];
    float rx = fmaxf(s * acc.x + bb.x, 0.f);
    float ry = fmaxf(s * acc.y + bb.y, 0.f);
    int b = d_batch[node];
    float* p = &d_pool[b * HIDDEN + lane * 2];
    asm volatile("red.global.add.v2.f32 [%0], {%1, %2};"
                 :: "l"(p), "f"(rx), "f"(ry) : "memory");
}

// ---------------- MLP head ------------------------------------------------------
__global__ void k_mlp(const float* __restrict__ Wm1, const float* __restrict__ bm1,
                      const float* __restrict__ Wm2, const float* __restrict__ bm2,
                      float* __restrict__ out) {
    __shared__ float sp[HIDDEN];
    __shared__ float sred[HIDDEN];
    int g = blockIdx.x, j = threadIdx.x;
    float inv = 1.0f / fmaxf(d_cnt[g], 1.0f);
    sp[j] = d_pool[g * HIDDEN + j] * inv;
    __syncthreads();
    float acc = bm1[j];
#pragma unroll
    for (int k = 0; k < HIDDEN; k++) acc += sp[k] * Wm1[k * HIDDEN + j];
    float v = fmaxf(acc, 0.f) * Wm2[j];
    sred[j] = v;
    __syncthreads();
    if (j < 32) {
        float t = sred[j] + sred[j + 32];
        for (int o = 16; o; o >>= 1) t += __shfl_down_sync(0xffffffff, t, o);
        if (j == 0) out[g] = t + bm2[0];
    }
}

// ---------------- launch --------------------------------------------------------
extern "C" void kernel_launch(void* const* d_in, const int* in_sizes, int n_in,
                              void* d_out, int out_size) {
    const float* x   = (const float*)d_in[0];
    const void*  ei  = d_in[1];
    const void*  bt  = d_in[2];
    const float* W1  = (const float*)d_in[3];
    const float* b1  = (const float*)d_in[4];
    const float* W2  = (const float*)d_in[5];
    const float* b2  = (const float*)d_in[6];
    const float* Wm1 = (const float*)d_in[7];
    const float* bm1 = (const float*)d_in[8];
    const float* Wm2 = (const float*)d_in[9];
    const float* bm2 = (const float*)d_in[10];
    float* out = (float*)d_out;

    // stream/events created once, on the (non-captured) correctness call
    static cudaStream_t s2 = nullptr;
    static cudaEvent_t evScan = nullptr, evFill = nullptr;
    if (!s2) {
        cudaStreamCreateWithFlags(&s2, cudaStreamNonBlocking);
        cudaEventCreateWithFlags(&evScan, cudaEventDisableTiming);
        cudaEventCreateWithFlags(&evFill, cudaEventDisableTiming);
    }

    k_prep<<<200, 256>>>((const int*)ei);
    k_convert<<<NB_CONV, 256>>>(ei, bt);
    k_scan<<<NB_SCAN, 256>>>();

    // fork: fill on s2 runs concurrently with gemm1 on the main stream
    cudaEventRecord(evScan, 0);
    cudaStreamWaitEvent(s2, evScan, 0);
    k_fill<<<NB_CONV, 256, 0, s2>>>();
    cudaEventRecord(evFill, s2);

    k_gemm1<<<NB_GEMM, 256>>>(x, W1);
    cudaStreamWaitEvent(0, evFill, 0);

    k_agg1<<<N_NODES / 16, 256>>>(b1, W2);
    k_agg2<<<N_NODES / 8, 256>>>(b2);
    k_mlp<<<N_GRAPHS, HIDDEN>>>(Wm1, bm1, Wm2, bm2, out);
}